// round 6
// baseline (speedup 1.0000x reference)
#include <cuda_runtime.h>
#include <cstdint>

// ---------------------------------------------------------------------------
// AnalogConv2d: 3x3 s1 p1, N=16 C=128 H=W=56 Cout=256, fp32 + bias.
// tf32 mma.sync.m16n8k8 implicit GEMM (compute_103-safe; no tcgen05).
// CTA tile 256(Cout) x 128(pos), 512 threads, 16 warps (4Mx4N),
// warp tile 64x32 -> 4 warps/SMSP for latency hiding (R4 had 2).
// K = 9 taps * 128 ch, chunked 32; 4-stage cp.async pipeline.
// ---------------------------------------------------------------------------

#define CIN    128
#define HWD    56
#define LSP    3136
#define COUT   256
#define NIMG   16
#define LTOT   (NIMG * LSP)      // 50176
#define TM     256
#define TN     128
#define NCTA   (LTOT / TN)       // 392
#define CHK    32
#define NCHUNK 36                // 9 taps * 4
#define STAGES 4
#define A_ST_B 32768u            // 256*32*4
#define B_ST_B 16384u            // 128*32*4
#define STG_B  (A_ST_B + B_ST_B) // 49152
#define SMEMB  (STAGES * STG_B)  // 196608 (192KB)

// Weights: fragment-major tf32: [tap][ck][mfrag16][ks4][lane32][4]
__device__ __align__(256) uint32_t g_Wt[9 * COUT * CIN];

__device__ __forceinline__ uint32_t f2tf32(float f) {
    uint32_t u;
    asm("cvt.rna.tf32.f32 %0, %1;" : "=r"(u) : "f"(f));
    return u;
}
__device__ __forceinline__ void cpa16(uint32_t d, const void* s) {
    asm volatile("cp.async.cg.shared.global [%0], [%1], 16;" :: "r"(d), "l"(s));
}
__device__ __forceinline__ void cpa4(uint32_t d, const void* s, uint32_t sz) {
    asm volatile("cp.async.ca.shared.global [%0], [%1], 4, %2;"
                 :: "r"(d), "l"(s), "r"(sz));
}
__device__ __forceinline__ void mma_tf32(float* d, const uint32_t* a,
                                         const uint32_t* b) {
    asm volatile(
        "mma.sync.aligned.m16n8k8.row.col.f32.tf32.tf32.f32 "
        "{%0,%1,%2,%3}, {%4,%5,%6,%7}, {%8,%9}, {%0,%1,%2,%3};"
        : "+f"(d[0]), "+f"(d[1]), "+f"(d[2]), "+f"(d[3])
        : "r"(a[0]), "r"(a[1]), "r"(a[2]), "r"(a[3]), "r"(b[0]), "r"(b[1]));
}

// ---------------------------------------------------------------------------
// w[co][c][3][3] -> g_Wt fragment-major (tf32 bits).
// idx = ((((tap*4+ck)*16+mf)*4+ks)*32+lane)*4 + r
// r0:(g,tig) r1:(g+8,tig) r2:(g,tig+4) r3:(g+8,tig+4)
// ---------------------------------------------------------------------------
__global__ void wt_transform_kernel(const float* __restrict__ w) {
    int idx = blockIdx.x * blockDim.x + threadIdx.x;
    if (idx >= 9 * COUT * CIN) return;
    int r    = idx & 3;
    int lane = (idx >> 2) & 31;
    int ks   = (idx >> 7) & 3;
    int mf   = (idx >> 9) & 15;
    int ck   = (idx >> 13) & 3;
    int tap  = idx >> 15;
    int g = lane >> 2, tig = lane & 3;
    int co = mf * 16 + g + 8 * (r & 1);
    int c  = ck * 32 + ks * 8 + tig + 4 * (r >> 1);
    g_Wt[idx] = f2tf32(w[(co * CIN + c) * 9 + tap]);
}

// ---------------------------------------------------------------------------
__global__ void __launch_bounds__(512, 1)
conv_mma_kernel(const float* __restrict__ x,
                const float* __restrict__ bias,
                float* __restrict__ out) {
    extern __shared__ float smem[];
    uint32_t sb;
    asm("{ .reg .u64 t; cvta.to.shared.u64 t, %1; cvt.u32.u64 %0, t; }"
        : "=r"(sb) : "l"(smem));

    const int tid  = threadIdx.x;
    const int wid  = tid >> 5;
    const int lane = tid & 31;
    const int wm   = wid >> 2;        // 0..3 : 64-row Cout band
    const int wn   = wid & 3;         // 0..3 : 32-col pos band
    const int g    = lane >> 2;
    const int tig  = lane & 3;

    const int l0 = blockIdx.x * TN;

    // ---- B gather setup: thread -> (pos, chb); 8 channels per thread ----
    const int pos = tid & 127;
    const int chb = tid >> 7;          // 0..3
    const int l   = l0 + pos;
    const int img = l / LSP;
    const int rl  = l - img * LSP;
    const int oh  = rl / HWD;
    const int ow  = rl - oh * HWD;
    const float* xb = x + (size_t)img * CIN * LSP;
    const uint32_t hsw = ((uint32_t)(pos & 7) << 2) | ((uint32_t)(pos >> 3) & 3);
    const uint32_t bdst_row = (uint32_t)pos * 32u;

    float acc[4][4][4];
    #pragma unroll
    for (int mi = 0; mi < 4; ++mi)
        #pragma unroll
        for (int ni = 0; ni < 4; ++ni)
            #pragma unroll
            for (int r2 = 0; r2 < 4; ++r2)
                acc[mi][ni][r2] = 0.0f;

    auto prefetch = [&](int q, int s) {
        const int tap = q >> 2;
        const int ck  = q & 3;
        const int ki  = tap / 3, kj = tap - ki * 3;
        const uint32_t sbase = sb + (uint32_t)s * STG_B;
        // A: 32KB contiguous fragment-major, 4 x 16B per thread
        const uint32_t* asrc = g_Wt + tap * 32768 + ck * 8192;
        #pragma unroll
        for (int i = 0; i < 4; ++i)
            cpa16(sbase + (uint32_t)(i * 512 + tid) * 16u,
                  asrc + (i * 512 + tid) * 4);
        // B: gather 8 channels (chb, chb+4, ...), XOR-swizzled dst
        const int ih = oh + ki - 1, iw = ow + kj - 1;
        const bool valid = ((unsigned)ih < HWD) & ((unsigned)iw < HWD);
        const float* src = valid
            ? (xb + (size_t)(ck * 32 + chb) * LSP + ih * HWD + iw) : x;
        const uint32_t sz = valid ? 4u : 0u;
        const uint32_t bb = sbase + A_ST_B;
        #pragma unroll
        for (int i = 0; i < 8; ++i) {
            uint32_t ch = (uint32_t)(chb + 4 * i);
            cpa4(bb + (bdst_row + (ch ^ hsw)) * 4u,
                 src + (size_t)(4 * i) * LSP, sz);
        }
    };

    auto compute = [&](int s) {
        const float4* A4 = (const float4*)(smem + s * (STG_B / 4));
        const float*  Bb = smem + s * (STG_B / 4) + (A_ST_B / 4);
        const uint32_t g4 = (uint32_t)g << 2;
        #pragma unroll
        for (int ks = 0; ks < 4; ++ks) {
            float4 af[4];
            #pragma unroll
            for (int mi = 0; mi < 4; ++mi)
                af[mi] = A4[((wm * 4 + mi) * 4 + ks) * 32 + lane];
            uint32_t bf[4][2];
            #pragma unroll
            for (int ni = 0; ni < 4; ++ni) {
                const uint32_t row = (uint32_t)(wn * 32 + ni * 8 + g) * 32u;
                const uint32_t sw  = g4 | (uint32_t)(ni & 3);
                const uint32_t k0  = (uint32_t)(ks * 8 + tig);
                bf[ni][0] = f2tf32(Bb[row + (k0 ^ sw)]);
                bf[ni][1] = f2tf32(Bb[row + ((k0 + 4) ^ sw)]);
            }
            #pragma unroll
            for (int mi = 0; mi < 4; ++mi) {
                uint32_t a_[4] = { __float_as_uint(af[mi].x),
                                   __float_as_uint(af[mi].y),
                                   __float_as_uint(af[mi].z),
                                   __float_as_uint(af[mi].w) };
                #pragma unroll
                for (int ni = 0; ni < 4; ++ni)
                    mma_tf32(acc[mi][ni], a_, bf[ni]);
            }
        }
    };

    // ---- 4-stage pipeline ----
    #pragma unroll
    for (int s = 0; s < STAGES - 1; ++s) {
        prefetch(s, s);
        asm volatile("cp.async.commit_group;" ::: "memory");
    }
    #pragma unroll 1
    for (int q = 0; q < NCHUNK; ++q) {
        asm volatile("cp.async.wait_group %0;" :: "n"(STAGES - 2) : "memory");
        __syncthreads();
        if (q + STAGES - 1 < NCHUNK)
            prefetch(q + STAGES - 1, (q + STAGES - 1) & (STAGES - 1));
        asm volatile("cp.async.commit_group;" ::: "memory");
        compute(q & (STAGES - 1));
    }

    // ---- epilogue: +bias, float2 stores ----
    const int co_base = wm * 64 + g;
    float bv[4][2];
    #pragma unroll
    for (int mi = 0; mi < 4; ++mi) {
        bv[mi][0] = bias[co_base + mi * 16];
        bv[mi][1] = bias[co_base + mi * 16 + 8];
    }
    #pragma unroll
    for (int ni = 0; ni < 4; ++ni) {
        const int le  = l0 + wn * 32 + ni * 8 + 2 * tig;
        const int im2 = le / LSP;
        const int rle = le - im2 * LSP;
        float* ob = out + (size_t)im2 * COUT * LSP + rle;
        #pragma unroll
        for (int mi = 0; mi < 4; ++mi) {
            #pragma unroll
            for (int h = 0; h < 2; ++h) {
                const int co = co_base + mi * 16 + h * 8;
                float2 v;
                v.x = acc[mi][ni][h * 2 + 0] + bv[mi][h];
                v.y = acc[mi][ni][h * 2 + 1] + bv[mi][h];
                *reinterpret_cast<float2*>(ob + (size_t)co * LSP) = v;
            }
        }
    }
}

// ---------------------------------------------------------------------------
extern "C" void kernel_launch(void* const* d_in, const int* in_sizes, int n_in,
                              void* d_out, int out_size) {
    const float* x    = (const float*)d_in[0];
    const float* w    = (const float*)d_in[1];
    const float* bias = (const float*)d_in[2];
    float* out = (float*)d_out;

    cudaFuncSetAttribute(conv_mma_kernel,
                         cudaFuncAttributeMaxDynamicSharedMemorySize, SMEMB);

    wt_transform_kernel<<<(9 * COUT * CIN + 255) / 256, 256>>>(w);
    conv_mma_kernel<<<NCTA, 512, SMEMB>>>(x, bias, out);
}

// round 7
// speedup vs baseline: 1.0284x; 1.0284x over previous
#include <cuda_runtime.h>
#include <cstdint>

// ---------------------------------------------------------------------------
// AnalogConv2d: 3x3 s1 p1, N=16 C=128 H=W=56 Cout=256, fp32 + bias.
// tf32 mma.sync.m16n8k8 implicit GEMM (compute_103-safe).
// CTA tile 128(Cout) x 128(pos), 256 threads, 8 warps (2Mx4N), warp 64x32.
// <=128 regs + 96KB smem -> 2 independent CTAs per SM (decoupled barriers).
// K = 9 taps * 128 ch, chunk 32; 3-stage cp.async pipeline.
// ---------------------------------------------------------------------------

#define CIN    128
#define HWD    56
#define LSP    3136
#define COUT   256
#define NIMG   16
#define LTOT   (NIMG * LSP)      // 50176
#define TM     128
#define TN     128
#define NCTA_X (LTOT / TN)       // 392
#define NCHUNK 36                // 9 taps * 4
#define STAGES 3
#define A_ST_B 16384u            // 128*32*4
#define B_ST_B 16384u            // 128*32*4
#define STG_B  (A_ST_B + B_ST_B) // 32768
#define SMEMB  (STAGES * STG_B)  // 98304 (96KB)

// Weights fragment-major per Cout-half:
// [tap][half][ck][mf8][ks4][lane32][4]  (16KB per (tap,half,ck))
__device__ __align__(256) uint32_t g_Wt[9 * COUT * CIN];

__device__ __forceinline__ uint32_t f2tf32(float f) {
    uint32_t u;
    asm("cvt.rna.tf32.f32 %0, %1;" : "=r"(u) : "f"(f));
    return u;
}
__device__ __forceinline__ void cpa16(uint32_t d, const void* s) {
    asm volatile("cp.async.cg.shared.global [%0], [%1], 16;" :: "r"(d), "l"(s));
}
__device__ __forceinline__ void cpa4(uint32_t d, const void* s, uint32_t sz) {
    asm volatile("cp.async.ca.shared.global [%0], [%1], 4, %2;"
                 :: "r"(d), "l"(s), "r"(sz));
}
__device__ __forceinline__ void mma_tf32(float* d, const uint32_t* a,
                                         const uint32_t* b) {
    asm volatile(
        "mma.sync.aligned.m16n8k8.row.col.f32.tf32.tf32.f32 "
        "{%0,%1,%2,%3}, {%4,%5,%6,%7}, {%8,%9}, {%0,%1,%2,%3};"
        : "+f"(d[0]), "+f"(d[1]), "+f"(d[2]), "+f"(d[3])
        : "r"(a[0]), "r"(a[1]), "r"(a[2]), "r"(a[3]), "r"(b[0]), "r"(b[1]));
}

// ---------------------------------------------------------------------------
// w[co][c][3][3] -> g_Wt fragment-major (tf32 bits).
// idx = (((((tap*2+half)*4+ck)*8+mf)*4+ks)*32+lane)*4 + r
// r0:(g,tig) r1:(g+8,tig) r2:(g,tig+4) r3:(g+8,tig+4)
// ---------------------------------------------------------------------------
__global__ void wt_transform_kernel(const float* __restrict__ w) {
    int idx = blockIdx.x * blockDim.x + threadIdx.x;
    if (idx >= 9 * COUT * CIN) return;
    int r    = idx & 3;
    int lane = (idx >> 2) & 31;
    int ks   = (idx >> 7) & 3;
    int mf   = (idx >> 9) & 7;
    int ck   = (idx >> 12) & 3;
    int half = (idx >> 14) & 1;
    int tap  = idx >> 15;
    int g = lane >> 2, tig = lane & 3;
    int co = half * 128 + mf * 16 + g + 8 * (r & 1);
    int c  = ck * 32 + ks * 8 + tig + 4 * (r >> 1);
    g_Wt[idx] = f2tf32(w[(co * CIN + c) * 9 + tap]);
}

// ---------------------------------------------------------------------------
__global__ void __launch_bounds__(256, 2)
conv_mma_kernel(const float* __restrict__ x,
                const float* __restrict__ bias,
                float* __restrict__ out) {
    extern __shared__ float smem[];
    uint32_t sb;
    asm("{ .reg .u64 t; cvta.to.shared.u64 t, %1; cvt.u32.u64 %0, t; }"
        : "=r"(sb) : "l"(smem));

    const int tid  = threadIdx.x;
    const int wid  = tid >> 5;
    const int lane = tid & 31;
    const int wm   = wid >> 2;        // 0..1 : 64-row Cout band
    const int wn   = wid & 3;         // 0..3 : 32-col pos band
    const int g    = lane >> 2;
    const int tig  = lane & 3;

    const int half = blockIdx.y;      // Cout half
    const int l0   = blockIdx.x * TN;

    // ---- B gather setup: thread -> (pos, chb); 16 channels stride 2 ----
    const int pos = tid & 127;
    const int chb = tid >> 7;          // 0..1
    const int l   = l0 + pos;
    const int img = l / LSP;
    const int rl  = l - img * LSP;
    const int oh  = rl / HWD;
    const int ow  = rl - oh * HWD;
    const float* xb = x + (size_t)img * CIN * LSP;
    const uint32_t hsw = ((uint32_t)(pos & 7) << 2) | ((uint32_t)(pos >> 3) & 3);
    const uint32_t bdst_row = (uint32_t)pos * 32u;

    float acc[4][4][4];
    #pragma unroll
    for (int mi = 0; mi < 4; ++mi)
        #pragma unroll
        for (int ni = 0; ni < 4; ++ni)
            #pragma unroll
            for (int r2 = 0; r2 < 4; ++r2)
                acc[mi][ni][r2] = 0.0f;

    auto prefetch = [&](int q, int s) {
        const int tap = q >> 2;
        const int ck  = q & 3;
        const int ki  = tap / 3, kj = tap - ki * 3;
        const uint32_t sbase = sb + (uint32_t)s * STG_B;
        // A: 16KB contiguous fragment-major for this (tap, half, ck)
        const uint32_t* asrc = g_Wt + (((tap * 2 + half) * 4 + ck) << 12);
        #pragma unroll
        for (int i = 0; i < 4; ++i)
            cpa16(sbase + (uint32_t)(i * 256 + tid) * 16u,
                  asrc + (i * 256 + tid) * 4);
        // B: gather 16 channels (chb, chb+2, ...), XOR-swizzled dst
        const int ih = oh + ki - 1, iw = ow + kj - 1;
        const bool valid = ((unsigned)ih < HWD) & ((unsigned)iw < HWD);
        const float* src = valid
            ? (xb + (size_t)(ck * 32 + chb) * LSP + ih * HWD + iw) : x;
        const uint32_t sz = valid ? 4u : 0u;
        const uint32_t bb = sbase + A_ST_B;
        #pragma unroll
        for (int i = 0; i < 16; ++i) {
            uint32_t ch = (uint32_t)(chb + 2 * i);
            cpa4(bb + (bdst_row + (ch ^ hsw)) * 4u,
                 src + (size_t)(2 * i) * LSP, sz);
        }
    };

    auto compute = [&](int s) {
        const float4* A4 = (const float4*)(smem + s * (STG_B / 4));
        const float*  Bb = smem + s * (STG_B / 4) + (A_ST_B / 4);
        const uint32_t g4 = (uint32_t)g << 2;
        #pragma unroll
        for (int ks = 0; ks < 4; ++ks) {
            float4 af[4];
            #pragma unroll
            for (int mi = 0; mi < 4; ++mi)
                af[mi] = A4[((wm * 4 + mi) * 4 + ks) * 32 + lane];
            uint32_t bf[4][2];
            #pragma unroll
            for (int ni = 0; ni < 4; ++ni) {
                const uint32_t row = (uint32_t)(wn * 32 + ni * 8 + g) * 32u;
                const uint32_t sw  = g4 | (uint32_t)ni;
                const uint32_t k0  = (uint32_t)(ks * 8 + tig);
                bf[ni][0] = f2tf32(Bb[row + (k0 ^ sw)]);
                bf[ni][1] = f2tf32(Bb[row + ((k0 + 4) ^ sw)]);
            }
            #pragma unroll
            for (int mi = 0; mi < 4; ++mi) {
                uint32_t a_[4] = { __float_as_uint(af[mi].x),
                                   __float_as_uint(af[mi].y),
                                   __float_as_uint(af[mi].z),
                                   __float_as_uint(af[mi].w) };
                #pragma unroll
                for (int ni = 0; ni < 4; ++ni)
                    mma_tf32(acc[mi][ni], a_, bf[ni]);
            }
        }
    };

    // ---- 3-stage pipeline ----
    #pragma unroll
    for (int s = 0; s < STAGES - 1; ++s) {
        prefetch(s, s);
        asm volatile("cp.async.commit_group;" ::: "memory");
    }
    int sidx = STAGES - 1;     // stage to prefetch into next
    int cidx = 0;              // stage to compute
    #pragma unroll 1
    for (int q = 0; q < NCHUNK; ++q) {
        asm volatile("cp.async.wait_group %0;" :: "n"(STAGES - 2) : "memory");
        __syncthreads();
        if (q + STAGES - 1 < NCHUNK)
            prefetch(q + STAGES - 1, sidx);
        asm volatile("cp.async.commit_group;" ::: "memory");
        compute(cidx);
        sidx = (sidx == STAGES - 1) ? 0 : sidx + 1;
        cidx = (cidx == STAGES - 1) ? 0 : cidx + 1;
    }

    // ---- epilogue: +bias, float2 stores ----
    const int co_base = half * 128 + wm * 64 + g;
    float bv[4][2];
    #pragma unroll
    for (int mi = 0; mi < 4; ++mi) {
        bv[mi][0] = bias[co_base + mi * 16];
        bv[mi][1] = bias[co_base + mi * 16 + 8];
    }
    #pragma unroll
    for (int ni = 0; ni < 4; ++ni) {
        const int le  = l0 + wn * 32 + ni * 8 + 2 * tig;
        const int im2 = le / LSP;
        const int rle = le - im2 * LSP;
        float* ob = out + (size_t)im2 * COUT * LSP + rle;
        #pragma unroll
        for (int mi = 0; mi < 4; ++mi) {
            #pragma unroll
            for (int h = 0; h < 2; ++h) {
                const int co = co_base + mi * 16 + h * 8;
                float2 v;
                v.x = acc[mi][ni][h * 2 + 0] + bv[mi][h];
                v.y = acc[mi][ni][h * 2 + 1] + bv[mi][h];
                *reinterpret_cast<float2*>(ob + (size_t)co * LSP) = v;
            }
        }
    }
}

// ---------------------------------------------------------------------------
extern "C" void kernel_launch(void* const* d_in, const int* in_sizes, int n_in,
                              void* d_out, int out_size) {
    const float* x    = (const float*)d_in[0];
    const float* w    = (const float*)d_in[1];
    const float* bias = (const float*)d_in[2];
    float* out = (float*)d_out;

    cudaFuncSetAttribute(conv_mma_kernel,
                         cudaFuncAttributeMaxDynamicSharedMemorySize, SMEMB);

    wt_transform_kernel<<<(9 * COUT * CIN + 255) / 256, 256>>>(w);
    dim3 grid(NCTA_X, 2, 1);
    conv_mma_kernel<<<grid, 256, SMEMB>>>(x, bias, out);
}

// round 8
// speedup vs baseline: 1.0446x; 1.0157x over previous
#include <cuda_runtime.h>
#include <cstdint>

// ---------------------------------------------------------------------------
// AnalogConv2d: 3x3 s1 p1, N=16 C=128 H=W=56 Cout=256, fp32 + bias.
// tf32 mma.sync.m16n8k8 implicit GEMM (compute_103-safe).
// CTA tile 256(Cout) x 128(pos), 8 warps (4Mx2N), warp tile 64x64.
// K chunked 64 (NCHUNK=18) -> half the chunk-boundary fixed costs of R4.
// 2-stage cp.async pipeline (96KB/stage), ONE syncthreads per chunk,
// prefetch issued before the wait.
// ---------------------------------------------------------------------------

#define CIN    128
#define HWD    56
#define LSP    3136
#define COUT   256
#define NIMG   16
#define LTOT   (NIMG * LSP)      // 50176
#define TM     256
#define TN     128
#define NCTA   (LTOT / TN)       // 392
#define CHK    64
#define NCHUNK 18                // 9 taps * 2
#define STAGES 2
#define A_ST_B 65536u            // 256*64*4
#define B_ST_B 32768u            // 128*64*4
#define STG_B  (A_ST_B + B_ST_B) // 98304
#define SMEMB  (STAGES * STG_B)  // 196608 (192KB)

// Weights fragment-major tf32: [tap][ck2][mf16][ks8][lane32][4]
__device__ __align__(256) uint32_t g_Wt[9 * COUT * CIN];

__device__ __forceinline__ uint32_t f2tf32(float f) {
    uint32_t u;
    asm("cvt.rna.tf32.f32 %0, %1;" : "=r"(u) : "f"(f));
    return u;
}
__device__ __forceinline__ void cpa16(uint32_t d, const void* s) {
    asm volatile("cp.async.cg.shared.global [%0], [%1], 16;" :: "r"(d), "l"(s));
}
__device__ __forceinline__ void cpa4(uint32_t d, const void* s, uint32_t sz) {
    asm volatile("cp.async.ca.shared.global [%0], [%1], 4, %2;"
                 :: "r"(d), "l"(s), "r"(sz));
}
__device__ __forceinline__ void mma_tf32(float* d, const uint32_t* a,
                                         const uint32_t* b) {
    asm volatile(
        "mma.sync.aligned.m16n8k8.row.col.f32.tf32.tf32.f32 "
        "{%0,%1,%2,%3}, {%4,%5,%6,%7}, {%8,%9}, {%0,%1,%2,%3};"
        : "+f"(d[0]), "+f"(d[1]), "+f"(d[2]), "+f"(d[3])
        : "r"(a[0]), "r"(a[1]), "r"(a[2]), "r"(a[3]), "r"(b[0]), "r"(b[1]));
}

// ---------------------------------------------------------------------------
// w[co][c][3][3] -> g_Wt fragment-major (tf32 bits).
// idx = ((((tap*2+ck)*16+mf)*8+ks)*32+lane)*4 + r
// r0:(g,tig) r1:(g+8,tig) r2:(g,tig+4) r3:(g+8,tig+4)
// ---------------------------------------------------------------------------
__global__ void wt_transform_kernel(const float* __restrict__ w) {
    int idx = blockIdx.x * blockDim.x + threadIdx.x;
    if (idx >= 9 * COUT * CIN) return;
    int r    = idx & 3;
    int lane = (idx >> 2) & 31;
    int ks   = (idx >> 7) & 7;
    int mf   = (idx >> 10) & 15;
    int ck   = (idx >> 14) & 1;
    int tap  = idx >> 15;
    int g = lane >> 2, tig = lane & 3;
    int co = mf * 16 + g + 8 * (r & 1);
    int c  = ck * 64 + ks * 8 + tig + 4 * (r >> 1);
    g_Wt[idx] = f2tf32(w[(co * CIN + c) * 9 + tap]);
}

// ---------------------------------------------------------------------------
__global__ void __launch_bounds__(256, 1)
conv_mma_kernel(const float* __restrict__ x,
                const float* __restrict__ bias,
                float* __restrict__ out) {
    extern __shared__ float smem[];
    uint32_t sb;
    asm("{ .reg .u64 t; cvta.to.shared.u64 t, %1; cvt.u32.u64 %0, t; }"
        : "=r"(sb) : "l"(smem));

    const int tid  = threadIdx.x;
    const int wid  = tid >> 5;
    const int lane = tid & 31;
    const int wm   = wid >> 1;        // 0..3 : 64-row Cout band
    const int wn   = wid & 1;         // 0..1 : 64-col pos band
    const int g    = lane >> 2;
    const int tig  = lane & 3;

    const int l0 = blockIdx.x * TN;

    // ---- B gather setup: thread -> (pos, chb); 32 channels stride 2 ----
    const int pos = tid & 127;
    const int chb = tid >> 7;          // 0..1
    const int l   = l0 + pos;
    const int img = l / LSP;
    const int rl  = l - img * LSP;
    const int oh  = rl / HWD;
    const int ow  = rl - oh * HWD;
    const float* xb = x + (size_t)img * CIN * LSP;
    const uint32_t hsw = ((uint32_t)(pos & 7) << 2) | ((uint32_t)(pos >> 3) & 3);
    const uint32_t bdst_row = (uint32_t)pos * 64u;

    float acc[4][8][4];
    #pragma unroll
    for (int mi = 0; mi < 4; ++mi)
        #pragma unroll
        for (int ni = 0; ni < 8; ++ni)
            #pragma unroll
            for (int r2 = 0; r2 < 4; ++r2)
                acc[mi][ni][r2] = 0.0f;

    auto prefetch = [&](int q, int s) {
        const int tap = q >> 1;
        const int ck  = q & 1;
        const int ki  = tap / 3, kj = tap - ki * 3;
        const uint32_t sbase = sb + (uint32_t)s * STG_B;
        // A: 64KB contiguous fragment-major, 16 x 16B per thread
        const uint32_t* asrc = g_Wt + ((tap * 2 + ck) << 14);
        #pragma unroll
        for (int i = 0; i < 16; ++i)
            cpa16(sbase + (uint32_t)(i * 256 + tid) * 16u,
                  asrc + (i * 256 + tid) * 4);
        // B: gather 32 channels (chb, chb+2, ...), XOR-swizzled dst
        const int ih = oh + ki - 1, iw = ow + kj - 1;
        const bool valid = ((unsigned)ih < HWD) & ((unsigned)iw < HWD);
        const float* src = valid
            ? (xb + (size_t)(ck * 64 + chb) * LSP + ih * HWD + iw) : x;
        const uint32_t sz = valid ? 4u : 0u;
        const uint32_t bb = sbase + A_ST_B;
        #pragma unroll
        for (int i = 0; i < 32; ++i) {
            uint32_t ch = (uint32_t)(chb + 2 * i);
            cpa4(bb + (bdst_row + (ch ^ hsw)) * 4u,
                 src + (size_t)(2 * i) * LSP, sz);
        }
    };

    auto compute = [&](int s) {
        const float4* A4 = (const float4*)(smem + s * (STG_B / 4));
        const float*  Bb = smem + s * (STG_B / 4) + (A_ST_B / 4);
        const uint32_t g4 = (uint32_t)g << 2;
        #pragma unroll
        for (int ks = 0; ks < 8; ++ks) {
            float4 af[4];
            #pragma unroll
            for (int mi = 0; mi < 4; ++mi)
                af[mi] = A4[((wm * 4 + mi) * 8 + ks) * 32 + lane];
            uint32_t bf[8][2];
            #pragma unroll
            for (int ni = 0; ni < 8; ++ni) {
                const uint32_t row = (uint32_t)(wn * 64 + ni * 8 + g) * 64u;
                const uint32_t sw  = g4 | (uint32_t)(ni & 3);
                const uint32_t k0  = (uint32_t)(ks * 8 + tig);
                bf[ni][0] = f2tf32(Bb[row + (k0 ^ sw)]);
                bf[ni][1] = f2tf32(Bb[row + ((k0 + 4) ^ sw)]);
            }
            #pragma unroll
            for (int mi = 0; mi < 4; ++mi) {
                uint32_t a_[4] = { __float_as_uint(af[mi].x),
                                   __float_as_uint(af[mi].y),
                                   __float_as_uint(af[mi].z),
                                   __float_as_uint(af[mi].w) };
                #pragma unroll
                for (int ni = 0; ni < 8; ++ni)
                    mma_tf32(acc[mi][ni], a_, bf[ni]);
            }
        }
    };

    // ---- 2-stage pipeline, one sync per chunk ----
    prefetch(0, 0);
    asm volatile("cp.async.commit_group;" ::: "memory");
    #pragma unroll 1
    for (int q = 0; q < NCHUNK; ++q) {
        __syncthreads();   // all warps done computing the stage we refill
        if (q + 1 < NCHUNK)
            prefetch(q + 1, (q + 1) & 1);
        asm volatile("cp.async.commit_group;" ::: "memory");
        asm volatile("cp.async.wait_group 1;" ::: "memory");
        __syncthreads();   // stage (q&1) visible to all warps
        compute(q & 1);
    }

    // ---- epilogue: +bias, float2 stores ----
    const int co_base = wm * 64 + g;
    float bv[4][2];
    #pragma unroll
    for (int mi = 0; mi < 4; ++mi) {
        bv[mi][0] = bias[co_base + mi * 16];
        bv[mi][1] = bias[co_base + mi * 16 + 8];
    }
    #pragma unroll
    for (int ni = 0; ni < 8; ++ni) {
        const int le  = l0 + wn * 64 + ni * 8 + 2 * tig;
        const int im2 = le / LSP;
        const int rle = le - im2 * LSP;
        float* ob = out + (size_t)im2 * COUT * LSP + rle;
        #pragma unroll
        for (int mi = 0; mi < 4; ++mi) {
            #pragma unroll
            for (int h = 0; h < 2; ++h) {
                const int co = co_base + mi * 16 + h * 8;
                float2 v;
                v.x = acc[mi][ni][h * 2 + 0] + bv[mi][h];
                v.y = acc[mi][ni][h * 2 + 1] + bv[mi][h];
                *reinterpret_cast<float2*>(ob + (size_t)co * LSP) = v;
            }
        }
    }
}

// ---------------------------------------------------------------------------
extern "C" void kernel_launch(void* const* d_in, const int* in_sizes, int n_in,
                              void* d_out, int out_size) {
    const float* x    = (const float*)d_in[0];
    const float* w    = (const float*)d_in[1];
    const float* bias = (const float*)d_in[2];
    float* out = (float*)d_out;

    cudaFuncSetAttribute(conv_mma_kernel,
                         cudaFuncAttributeMaxDynamicSharedMemorySize, SMEMB);

    wt_transform_kernel<<<(9 * COUT * CIN + 255) / 256, 256>>>(w);
    conv_mma_kernel<<<NCTA, 256, SMEMB>>>(x, bias, out);
}

// round 9
// speedup vs baseline: 1.0856x; 1.0392x over previous
#include <cuda_runtime.h>
#include <cstdint>

// ---------------------------------------------------------------------------
// AnalogConv2d: 3x3 s1 p1, N=16 C=128 H=W=56 Cout=256, fp32 + bias.
// tf32 mma.sync.m16n8k8 implicit GEMM (compute_103-safe).
// CTA tile 256(Cout) x 128(pos), 8 warps (4Mx2N), warp tile 64x64.
// R8: x pre-converted to tf32 in device scratch (no cvt in inner loop),
// explicit ks software pipeline with register double-buffered fragments.
// K chunk 64, 2-stage cp.async pipeline (96KB/stage).
// ---------------------------------------------------------------------------

#define CIN    128
#define HWD    56
#define LSP    3136
#define COUT   256
#define NIMG   16
#define LTOT   (NIMG * LSP)      // 50176
#define XTOT   (NIMG * CIN * LSP) // 6422528
#define TM     256
#define TN     128
#define NCTA   (LTOT / TN)       // 392
#define NCHUNK 18                // 9 taps * 2 (CHK=64)
#define A_ST_B 65536u            // 256*64*4
#define B_ST_B 32768u            // 128*64*4
#define STG_B  (A_ST_B + B_ST_B) // 98304
#define SMEMB  (2 * STG_B)       // 196608 (192KB)

// Weights fragment-major tf32: [tap][ck2][mf16][ks8][lane32][4]
__device__ __align__(256) uint32_t g_Wt[9 * COUT * CIN];
// x pre-converted to tf32 bits, same [img][c][h][w] layout
__device__ __align__(256) uint32_t g_Xt[XTOT];

__device__ __forceinline__ uint32_t f2tf32(float f) {
    uint32_t u;
    asm("cvt.rna.tf32.f32 %0, %1;" : "=r"(u) : "f"(f));
    return u;
}
__device__ __forceinline__ void cpa16(uint32_t d, const void* s) {
    asm volatile("cp.async.cg.shared.global [%0], [%1], 16;" :: "r"(d), "l"(s));
}
__device__ __forceinline__ void cpa4(uint32_t d, const void* s, uint32_t sz) {
    asm volatile("cp.async.ca.shared.global [%0], [%1], 4, %2;"
                 :: "r"(d), "l"(s), "r"(sz));
}
__device__ __forceinline__ void mma_tf32(float* d, const uint32_t* a,
                                         const uint32_t* b) {
    asm volatile(
        "mma.sync.aligned.m16n8k8.row.col.f32.tf32.tf32.f32 "
        "{%0,%1,%2,%3}, {%4,%5,%6,%7}, {%8,%9}, {%0,%1,%2,%3};"
        : "+f"(d[0]), "+f"(d[1]), "+f"(d[2]), "+f"(d[3])
        : "r"(a[0]), "r"(a[1]), "r"(a[2]), "r"(a[3]), "r"(b[0]), "r"(b[1]));
}

// ---------------------------------------------------------------------------
// w[co][c][3][3] -> g_Wt fragment-major (tf32 bits).
// idx = ((((tap*2+ck)*16+mf)*8+ks)*32+lane)*4 + r
// r0:(g,tig) r1:(g+8,tig) r2:(g,tig+4) r3:(g+8,tig+4)
// ---------------------------------------------------------------------------
__global__ void wt_transform_kernel(const float* __restrict__ w) {
    int idx = blockIdx.x * blockDim.x + threadIdx.x;
    if (idx >= 9 * COUT * CIN) return;
    int r    = idx & 3;
    int lane = (idx >> 2) & 31;
    int ks   = (idx >> 7) & 7;
    int mf   = (idx >> 10) & 15;
    int ck   = (idx >> 14) & 1;
    int tap  = idx >> 15;
    int g = lane >> 2, tig = lane & 3;
    int co = mf * 16 + g + 8 * (r & 1);
    int c  = ck * 64 + ks * 8 + tig + 4 * (r >> 1);
    g_Wt[idx] = f2tf32(w[(co * CIN + c) * 9 + tap]);
}

// x fp32 -> g_Xt tf32 bits (vectorized)
__global__ void x_transform_kernel(const float* __restrict__ x) {
    int i = blockIdx.x * blockDim.x + threadIdx.x;
    if (i < XTOT / 4) {
        float4 v = reinterpret_cast<const float4*>(x)[i];
        uint4 o;
        o.x = f2tf32(v.x); o.y = f2tf32(v.y);
        o.z = f2tf32(v.z); o.w = f2tf32(v.w);
        reinterpret_cast<uint4*>(g_Xt)[i] = o;
    }
}

// ---------------------------------------------------------------------------
__global__ void __launch_bounds__(256, 1)
conv_mma_kernel(const float* __restrict__ bias,
                float* __restrict__ out) {
    extern __shared__ float smem[];
    uint32_t sb;
    asm("{ .reg .u64 t; cvta.to.shared.u64 t, %1; cvt.u32.u64 %0, t; }"
        : "=r"(sb) : "l"(smem));

    const int tid  = threadIdx.x;
    const int wid  = tid >> 5;
    const int lane = tid & 31;
    const int wm   = wid >> 1;        // 0..3 : 64-row Cout band
    const int wn   = wid & 1;         // 0..1 : 64-col pos band
    const int g    = lane >> 2;
    const int tig  = lane & 3;

    const int l0 = blockIdx.x * TN;

    // ---- B gather setup: thread -> (pos, chb); 32 channels stride 2 ----
    const int pos = tid & 127;
    const int chb = tid >> 7;          // 0..1
    const int l   = l0 + pos;
    const int img = l / LSP;
    const int rl  = l - img * LSP;
    const int oh  = rl / HWD;
    const int ow  = rl - oh * HWD;
    const uint32_t* xb = g_Xt + (size_t)img * CIN * LSP;
    const uint32_t hsw = ((uint32_t)(pos & 7) << 2) | ((uint32_t)(pos >> 3) & 3);
    const uint32_t bdst_row = (uint32_t)pos * 64u;

    float acc[4][8][4];
    #pragma unroll
    for (int mi = 0; mi < 4; ++mi)
        #pragma unroll
        for (int ni = 0; ni < 8; ++ni)
            #pragma unroll
            for (int r2 = 0; r2 < 4; ++r2)
                acc[mi][ni][r2] = 0.0f;

    auto prefetch = [&](int q, int s) {
        const int tap = q >> 1;
        const int ck  = q & 1;
        const int ki  = tap / 3, kj = tap - ki * 3;
        const uint32_t sbase = sb + (uint32_t)s * STG_B;
        // A: 64KB contiguous fragment-major, 16 x 16B per thread
        const uint32_t* asrc = g_Wt + ((tap * 2 + ck) << 14);
        #pragma unroll
        for (int i = 0; i < 16; ++i)
            cpa16(sbase + (uint32_t)(i * 256 + tid) * 16u,
                  asrc + (i * 256 + tid) * 4);
        // B: gather 32 tf32 channels (chb, chb+2, ...), XOR-swizzled dst
        const int ih = oh + ki - 1, iw = ow + kj - 1;
        const bool valid = ((unsigned)ih < HWD) & ((unsigned)iw < HWD);
        const uint32_t* src = valid
            ? (xb + (size_t)(ck * 64 + chb) * LSP + ih * HWD + iw) : g_Xt;
        const uint32_t sz = valid ? 4u : 0u;
        const uint32_t bb = sbase + A_ST_B;
        #pragma unroll
        for (int i = 0; i < 32; ++i) {
            uint32_t ch = (uint32_t)(chb + 2 * i);
            cpa4(bb + (bdst_row + (ch ^ hsw)) * 4u,
                 src + (size_t)(2 * i) * LSP, sz);
        }
    };

    auto compute = [&](int s) {
        const uint4*    A4 = (const uint4*)(smem + s * (STG_B / 4));
        const uint32_t* Bb = (const uint32_t*)(smem + s * (STG_B / 4)
                                               + (A_ST_B / 4));
        const uint32_t g4 = (uint32_t)g << 2;

        uint4    af[2][4];
        uint32_t bf[2][8][2];
        auto ldf = [&](int ks, int b) {
            #pragma unroll
            for (int mi = 0; mi < 4; ++mi)
                af[b][mi] = A4[((wm * 4 + mi) * 8 + ks) * 32 + lane];
            #pragma unroll
            for (int ni = 0; ni < 8; ++ni) {
                const uint32_t row = (uint32_t)(wn * 64 + ni * 8 + g) * 64u;
                const uint32_t sw  = g4 | (uint32_t)(ni & 3);
                const uint32_t k0  = (uint32_t)(ks * 8 + tig);
                bf[b][ni][0] = Bb[row + (k0 ^ sw)];
                bf[b][ni][1] = Bb[row + ((k0 + 4) ^ sw)];
            }
        };

        ldf(0, 0);
        #pragma unroll
        for (int ks = 0; ks < 8; ++ks) {
            const int cur = ks & 1;
            if (ks < 7) ldf(ks + 1, cur ^ 1);
            #pragma unroll
            for (int mi = 0; mi < 4; ++mi) {
                uint32_t a_[4] = { af[cur][mi].x, af[cur][mi].y,
                                   af[cur][mi].z, af[cur][mi].w };
                #pragma unroll
                for (int ni = 0; ni < 8; ++ni)
                    mma_tf32(acc[mi][ni], a_, bf[cur][ni]);
            }
        }
    };

    // ---- 2-stage pipeline ----
    prefetch(0, 0);
    asm volatile("cp.async.commit_group;" ::: "memory");
    #pragma unroll 1
    for (int q = 0; q < NCHUNK; ++q) {
        __syncthreads();   // all warps done computing the stage we refill
        if (q + 1 < NCHUNK)
            prefetch(q + 1, (q + 1) & 1);
        asm volatile("cp.async.commit_group;" ::: "memory");
        asm volatile("cp.async.wait_group 1;" ::: "memory");
        __syncthreads();   // stage (q&1) visible to all warps
        compute(q & 1);
    }

    // ---- epilogue: +bias, float2 stores ----
    const int co_base = wm * 64 + g;
    float bv[4][2];
    #pragma unroll
    for (int mi = 0; mi < 4; ++mi) {
        bv[mi][0] = bias[co_base + mi * 16];
        bv[mi][1] = bias[co_base + mi * 16 + 8];
    }
    #pragma unroll
    for (int ni = 0; ni < 8; ++ni) {
        const int le  = l0 + wn * 64 + ni * 8 + 2 * tig;
        const int im2 = le / LSP;
        const int rle = le - im2 * LSP;
        float* ob = out + (size_t)im2 * COUT * LSP + rle;
        #pragma unroll
        for (int mi = 0; mi < 4; ++mi) {
            #pragma unroll
            for (int h = 0; h < 2; ++h) {
                const int co = co_base + mi * 16 + h * 8;
                float2 v;
                v.x = acc[mi][ni][h * 2 + 0] + bv[mi][h];
                v.y = acc[mi][ni][h * 2 + 1] + bv[mi][h];
                *reinterpret_cast<float2*>(ob + (size_t)co * LSP) = v;
            }
        }
    }
}

// ---------------------------------------------------------------------------
extern "C" void kernel_launch(void* const* d_in, const int* in_sizes, int n_in,
                              void* d_out, int out_size) {
    const float* x    = (const float*)d_in[0];
    const float* w    = (const float*)d_in[1];
    const float* bias = (const float*)d_in[2];
    float* out = (float*)d_out;

    cudaFuncSetAttribute(conv_mma_kernel,
                         cudaFuncAttributeMaxDynamicSharedMemorySize, SMEMB);

    wt_transform_kernel<<<(9 * COUT * CIN + 255) / 256, 256>>>(w);
    x_transform_kernel<<<(XTOT / 4 + 255) / 256, 256>>>(x);
    conv_mma_kernel<<<NCTA, 256, SMEMB>>>(bias, out);
}

// round 10
// speedup vs baseline: 1.8788x; 1.7307x over previous
#include <cuda_runtime.h>
#include <cuda_fp16.h>
#include <cstdint>

// ---------------------------------------------------------------------------
// AnalogConv2d: 3x3 s1 p1, N=16 C=128 H=W=56 Cout=256, fp32 + bias.
// fp16 mma.sync.m16n8k16 (fp32 accum) implicit GEMM — same 10-bit mantissa
// as tf32 (rel_err ~3e-4) at 2x the tensor throughput and half the memory.
// CTA tile 256(Cout) x 128(pos), 8 warps (4Mx2N), warp tile 64x64.
// K = 9 taps * 128 ch, chunk 64 (NCHUNK=18); 4-stage cp.async pipeline
// (48KB/stage), one syncthreads per chunk, register-double-buffered frags.
// x pre-packed to half2 channel pairs; weights fragment-major fp16.
// ---------------------------------------------------------------------------

#define CIN    128
#define HWD    56
#define LSP    3136
#define COUT   256
#define NIMG   16
#define LTOT   (NIMG * LSP)        // 50176
#define XPAIRS (NIMG * 64 * LSP)   // 3211264 half2 words
#define TM     256
#define TN     128
#define NCTA   (LTOT / TN)         // 392
#define NCHUNK 18                  // 9 taps * 2 (CHK=64 channels)
#define STAGES 4
#define A_ST_B 32768u              // 256*64*2
#define B_ST_B 16384u              // 128*64*2
#define STG_B  (A_ST_B + B_ST_B)   // 49152
#define SMEMB  (STAGES * STG_B)    // 196608 (192KB)

// Weights fragment-major fp16 pairs: [tap][ck2][mf16][ks4][lane32][4regs]
__device__ __align__(256) uint32_t g_Wh[9 * 2 * 16 * 4 * 32 * 4];
// x packed half2 channel pairs: [img][c2(64)][l(3136)]
__device__ __align__(256) uint32_t g_Xh[XPAIRS];

__device__ __forceinline__ void cpa16(uint32_t d, const void* s) {
    asm volatile("cp.async.cg.shared.global [%0], [%1], 16;" :: "r"(d), "l"(s));
}
__device__ __forceinline__ void cpa4(uint32_t d, const void* s, uint32_t sz) {
    asm volatile("cp.async.ca.shared.global [%0], [%1], 4, %2;"
                 :: "r"(d), "l"(s), "r"(sz));
}
__device__ __forceinline__ void mma_f16(float* d, const uint32_t* a,
                                        const uint32_t* b) {
    asm volatile(
        "mma.sync.aligned.m16n8k16.row.col.f32.f16.f16.f32 "
        "{%0,%1,%2,%3}, {%4,%5,%6,%7}, {%8,%9}, {%0,%1,%2,%3};"
        : "+f"(d[0]), "+f"(d[1]), "+f"(d[2]), "+f"(d[3])
        : "r"(a[0]), "r"(a[1]), "r"(a[2]), "r"(a[3]), "r"(b[0]), "r"(b[1]));
}

// ---------------------------------------------------------------------------
// w[co][c][3][3] -> g_Wh fragment-major fp16 pairs.
// idx = ((((tap*2+ck)*16+mf)*4+ks)*32+lane)*4 + r
// m16n8k16 A frag: r0:(g, 2tig) r1:(g+8, 2tig) r2:(g, 2tig+8) r3:(g+8, 2tig+8)
// each entry packs channels (c, c+1).
// ---------------------------------------------------------------------------
__global__ void wt_transform_kernel(const float* __restrict__ w) {
    int idx = blockIdx.x * blockDim.x + threadIdx.x;
    if (idx >= 9 * 2 * 16 * 4 * 32 * 4) return;
    int r    = idx & 3;
    int lane = (idx >> 2) & 31;
    int ks   = (idx >> 7) & 3;
    int mf   = (idx >> 9) & 15;
    int ck   = (idx >> 13) & 1;
    int tap  = idx >> 14;
    int g = lane >> 2, tig = lane & 3;
    int co = mf * 16 + g + 8 * (r & 1);
    int c  = ck * 64 + ks * 16 + 2 * tig + 8 * (r >> 1);
    __half2 v = __floats2half2_rn(w[(co * CIN + c) * 9 + tap],
                                  w[(co * CIN + c + 1) * 9 + tap]);
    g_Wh[idx] = *reinterpret_cast<uint32_t*>(&v);
}

// x fp32 [img][c][l] -> g_Xh half2 [img][c2][l] (channels 2c2, 2c2+1)
__global__ void x_transform_kernel(const float* __restrict__ x) {
    int i = blockIdx.x * blockDim.x + threadIdx.x;
    if (i >= XPAIRS) return;
    int l  = i % LSP;
    int t  = i / LSP;
    int c2 = t & 63;
    int im = t >> 6;
    const float* p = x + ((size_t)im * CIN + 2 * c2) * LSP + l;
    __half2 v = __floats2half2_rn(p[0], p[LSP]);
    g_Xh[i] = *reinterpret_cast<uint32_t*>(&v);
}

// ---------------------------------------------------------------------------
__global__ void __launch_bounds__(256, 1)
conv_mma_kernel(const float* __restrict__ bias,
                float* __restrict__ out) {
    extern __shared__ float smem[];
    uint32_t sb;
    asm("{ .reg .u64 t; cvta.to.shared.u64 t, %1; cvt.u32.u64 %0, t; }"
        : "=r"(sb) : "l"(smem));

    const int tid  = threadIdx.x;
    const int wid  = tid >> 5;
    const int lane = tid & 31;
    const int wm   = wid >> 1;        // 0..3 : 64-row Cout band
    const int wn   = wid & 1;         // 0..1 : 64-col pos band
    const int g    = lane >> 2;
    const int tig  = lane & 3;

    const int l0 = blockIdx.x * TN;

    // ---- B gather setup: thread -> (pos, c2b); 16 pair-granules each ----
    const int pos = tid & 127;
    const int c2b = tid >> 7;          // 0..1
    const int l   = l0 + pos;
    const int img = l / LSP;
    const int rl  = l - img * LSP;
    const int oh  = rl / HWD;
    const int ow  = rl - oh * HWD;
    const uint32_t* xb = g_Xh + (size_t)img * 64 * LSP;
    const uint32_t hsw = ((uint32_t)(pos & 7) << 2) | ((uint32_t)(pos >> 3) & 3);
    const uint32_t bdst_row = (uint32_t)pos * 32u;   // 32 granules/row

    float acc[4][8][4];
    #pragma unroll
    for (int mi = 0; mi < 4; ++mi)
        #pragma unroll
        for (int ni = 0; ni < 8; ++ni)
            #pragma unroll
            for (int r2 = 0; r2 < 4; ++r2)
                acc[mi][ni][r2] = 0.0f;

    auto prefetch = [&](int q, int s) {
        const int tap = q >> 1;
        const int ck  = q & 1;
        const int ki  = tap / 3, kj = tap - ki * 3;
        const uint32_t sbase = sb + (uint32_t)s * STG_B;
        // A: 32KB contiguous fragment-major, 8 x 16B per thread
        const uint32_t* asrc = g_Wh + (((size_t)(tap * 2 + ck)) << 13);
        #pragma unroll
        for (int i = 0; i < 8; ++i)
            cpa16(sbase + (uint32_t)(i * 256 + tid) * 16u,
                  asrc + (i * 256 + tid) * 4);
        // B: gather 16 half2 granules (c2b, c2b+2, ...), XOR-swizzled dst
        const int ih = oh + ki - 1, iw = ow + kj - 1;
        const bool valid = ((unsigned)ih < HWD) & ((unsigned)iw < HWD);
        const uint32_t* src = valid
            ? (xb + (size_t)(ck * 32 + c2b) * LSP + ih * HWD + iw) : g_Xh;
        const uint32_t sz = valid ? 4u : 0u;
        const uint32_t bb = sbase + A_ST_B;
        #pragma unroll
        for (int i = 0; i < 16; ++i) {
            uint32_t c2 = (uint32_t)(c2b + 2 * i);
            cpa4(bb + (bdst_row + (c2 ^ hsw)) * 4u,
                 src + (size_t)(2 * i) * LSP, sz);
        }
    };

    auto compute = [&](int s) {
        const uint4*    A4 = (const uint4*)(smem + s * (STG_B / 4));
        const uint32_t* Bb = (const uint32_t*)(smem + s * (STG_B / 4)
                                               + (A_ST_B / 4));
        const uint32_t g4 = (uint32_t)g << 2;

        uint4    af[2][4];
        uint32_t bf[2][8][2];
        auto ldf = [&](int ks, int b) {
            #pragma unroll
            for (int mi = 0; mi < 4; ++mi)
                af[b][mi] = A4[((wm * 4 + mi) * 4 + ks) * 32 + lane];
            #pragma unroll
            for (int ni = 0; ni < 8; ++ni) {
                const uint32_t row = (uint32_t)(wn * 64 + ni * 8 + g) * 32u;
                const uint32_t sw  = g4 | (uint32_t)(ni & 3);
                const uint32_t k0  = (uint32_t)(ks * 8 + tig);
                bf[b][ni][0] = Bb[row + (k0 ^ sw)];
                bf[b][ni][1] = Bb[row + ((k0 + 4) ^ sw)];
            }
        };

        ldf(0, 0);
        #pragma unroll
        for (int ks = 0; ks < 4; ++ks) {
            const int cur = ks & 1;
            if (ks < 3) ldf(ks + 1, cur ^ 1);
            #pragma unroll
            for (int mi = 0; mi < 4; ++mi) {
                uint32_t a_[4] = { af[cur][mi].x, af[cur][mi].y,
                                   af[cur][mi].z, af[cur][mi].w };
                #pragma unroll
                for (int ni = 0; ni < 8; ++ni)
                    mma_f16(acc[mi][ni], a_, bf[cur][ni]);
            }
        }
    };

    // ---- 4-stage pipeline, one sync per chunk ----
    #pragma unroll
    for (int s = 0; s < STAGES - 1; ++s) {
        prefetch(s, s);
        asm volatile("cp.async.commit_group;" ::: "memory");
    }
    #pragma unroll 1
    for (int q = 0; q < NCHUNK; ++q) {
        asm volatile("cp.async.wait_group %0;" :: "n"(STAGES - 2) : "memory");
        __syncthreads();   // stage q&3 visible; slot (q+3)&3 free to refill
        if (q + STAGES - 1 < NCHUNK)
            prefetch(q + STAGES - 1, (q + STAGES - 1) & (STAGES - 1));
        asm volatile("cp.async.commit_group;" ::: "memory");
        compute(q & (STAGES - 1));
    }

    // ---- epilogue: +bias, float2 stores ----
    const int co_base = wm * 64 + g;
    float bv[4][2];
    #pragma unroll
    for (int mi = 0; mi < 4; ++mi) {
        bv[mi][0] = bias[co_base + mi * 16];
        bv[mi][1] = bias[co_base + mi * 16 + 8];
    }
    #pragma unroll
    for (int ni = 0; ni < 8; ++ni) {
        const int le  = l0 + wn * 64 + ni * 8 + 2 * tig;
        const int im2 = le / LSP;
        const int rle = le - im2 * LSP;
        float* ob = out + (size_t)im2 * COUT * LSP + rle;
        #pragma unroll
        for (int mi = 0; mi < 4; ++mi) {
            #pragma unroll
            for (int h = 0; h < 2; ++h) {
                const int co = co_base + mi * 16 + h * 8;
                float2 v;
                v.x = acc[mi][ni][h * 2 + 0] + bv[mi][h];
                v.y = acc[mi][ni][h * 2 + 1] + bv[mi][h];
                *reinterpret_cast<float2*>(ob + (size_t)co * LSP) = v;
            }
        }
    }
}

// ---------------------------------------------------------------------------
extern "C" void kernel_launch(void* const* d_in, const int* in_sizes, int n_in,
                              void* d_out, int out_size) {
    const float* x    = (const float*)d_in[0];
    const float* w    = (const float*)d_in[1];
    const float* bias = (const float*)d_in[2];
    float* out = (float*)d_out;

    cudaFuncSetAttribute(conv_mma_kernel,
                         cudaFuncAttributeMaxDynamicSharedMemorySize, SMEMB);

    wt_transform_kernel<<<(9 * 2 * 16 * 4 * 32 * 4 + 255) / 256, 256>>>(w);
    x_transform_kernel<<<(XPAIRS + 255) / 256, 256>>>(x);
    conv_mma_kernel<<<NCTA, 256, SMEMB>>>(bias, out);
}